// round 5
// baseline (speedup 1.0000x reference)
#include <cuda_runtime.h>
#include <cuda_bf16.h>
#include <cstdint>

// Problem constants
#define DIMX 768
#define HQ   8
#define HKV  2
#define HD   64
#define SEQ  4096
#define NREP (HQ / HKV)   // 4

// Scratch (allocation-free rule: __device__ globals)
__device__ float g_Q[SEQ * HQ * HD];        // [4096, 512]
__device__ float g_K[SEQ * HKV * HD];       // [4096, 128]
__device__ float g_V[SEQ * HKV * HD];       // [4096, 128]
__device__ float g_C[SEQ * HQ * HD];        // context [4096, 512]
__device__ float g_rowsum[HQ * SEQ];        // exp row sums

// ===========================================================================
// tf32 helpers
// ===========================================================================
__device__ __forceinline__ float f2tf32(float x) {
    uint32_t u;
    asm("cvt.rna.tf32.f32 %0, %1;" : "=r"(u) : "f"(x));
    return __uint_as_float(u);
}
__device__ __forceinline__ uint32_t f2tf32_bits(float x) {
    uint32_t u;
    asm("cvt.rna.tf32.f32 %0, %1;" : "=r"(u) : "f"(x));
    return u;
}
__device__ __forceinline__ float4 tf32x4(float4 v) {
    float4 w;
    w.x = f2tf32(v.x); w.y = f2tf32(v.y); w.z = f2tf32(v.z); w.w = f2tf32(v.w);
    return w;
}

// m16n8k8 tf32 mma: D += A*B  (row.col)
__device__ __forceinline__ void mma_tf32(float* c, const uint32_t* a, const uint32_t* b) {
    asm volatile(
        "mma.sync.aligned.m16n8k8.row.col.f32.tf32.tf32.f32 "
        "{%0,%1,%2,%3}, {%4,%5,%6,%7}, {%8,%9}, {%0,%1,%2,%3};"
        : "+f"(c[0]), "+f"(c[1]), "+f"(c[2]), "+f"(c[3])
        : "r"(a[0]), "r"(a[1]), "r"(a[2]), "r"(a[3]), "r"(b[0]), "r"(b[1]));
}

__device__ __forceinline__ uint32_t fbits(float x) { return __float_as_uint(x); }

#define APAD 68   // row-major [row][k] tiles
#define BPAD 72   // k-major  [k][n] tiles

// ===========================================================================
// Pass 1: rowsum[h, m] = sum_n exp(Q_h.K_n / 8).  No att store.
// Tile M=128 x N=128 per iter. Warps 2(m) x 4(n).
// ===========================================================================
#define RS_QS 0
#define RS_KS (128 * APAD)
#define RS_RS (RS_KS + 128 * APAD)
#define RS_SMEM_BYTES ((RS_RS + 128) * 4)

__global__ __launch_bounds__(256, 2) void rowsum_kernel(
    const float* __restrict__ Q, const float* __restrict__ Km,
    float* __restrict__ rowsum)
{
    extern __shared__ float sm[];
    float* Qs = sm + RS_QS;
    float* Ks = sm + RS_KS;
    float* rsums = sm + RS_RS;

    const int t = threadIdx.x, lane = t & 31, wid = t >> 5;
    const int wm = wid >> 2, wn = wid & 3;
    const int g = lane >> 2, t4 = lane & 3;
    const int m0 = blockIdx.x * 128, h = blockIdx.y, kh = h / NREP;

#pragma unroll
    for (int i = 0; i < 8; i++) {
        int e = t + i * 256;
        int r = e >> 4, q = e & 15;
        float4 v = *(const float4*)(Q + (size_t)(m0 + r) * (HQ * HD) + h * HD + q * 4);
        *(float4*)&Qs[r * APAD + q * 4] = tf32x4(v);
    }
    if (t < 128) rsums[t] = 0.f;

    float rs[4][2];
#pragma unroll
    for (int i = 0; i < 4; i++) { rs[i][0] = 0.f; rs[i][1] = 0.f; }
    __syncthreads();

    for (int it = 0; it < SEQ / 128; it++) {
        const int n0 = it * 128;
        float4 kv[8];
#pragma unroll
        for (int i = 0; i < 8; i++) {
            int e = t + i * 256;
            int r = e >> 4, q = e & 15;
            kv[i] = tf32x4(*(const float4*)(Km + (size_t)(n0 + r) * (HKV * HD) + kh * HD + q * 4));
        }
        __syncthreads();
#pragma unroll
        for (int i = 0; i < 8; i++) {
            int e = t + i * 256;
            int r = e >> 4, q = e & 15;
            *(float4*)&Ks[r * APAD + q * 4] = kv[i];
        }
        __syncthreads();

        float acc[4][4][4];
#pragma unroll
        for (int i = 0; i < 4; i++)
#pragma unroll
            for (int j = 0; j < 4; j++)
#pragma unroll
                for (int c = 0; c < 4; c++) acc[i][j][c] = 0.f;

#pragma unroll
        for (int ks = 0; ks < 8; ks++) {
            const int kk = ks * 8;
            uint32_t B[4][2];
#pragma unroll
            for (int j = 0; j < 4; j++) {
                int n = wn * 32 + j * 8 + g;
                B[j][0] = fbits(Ks[n * APAD + kk + t4]);
                B[j][1] = fbits(Ks[n * APAD + kk + t4 + 4]);
            }
#pragma unroll
            for (int i = 0; i < 4; i++) {
                int r = wm * 64 + i * 16 + g;
                uint32_t A[4] = {
                    fbits(Qs[r * APAD + kk + t4]),
                    fbits(Qs[(r + 8) * APAD + kk + t4]),
                    fbits(Qs[r * APAD + kk + t4 + 4]),
                    fbits(Qs[(r + 8) * APAD + kk + t4 + 4]) };
#pragma unroll
                for (int j = 0; j < 4; j++) mma_tf32(acc[i][j], A, B[j]);
            }
        }

#pragma unroll
        for (int i = 0; i < 4; i++)
#pragma unroll
            for (int j = 0; j < 4; j++) {
                rs[i][0] += __expf(acc[i][j][0] * 0.125f) + __expf(acc[i][j][1] * 0.125f);
                rs[i][1] += __expf(acc[i][j][2] * 0.125f) + __expf(acc[i][j][3] * 0.125f);
            }
    }

#pragma unroll
    for (int i = 0; i < 4; i++)
#pragma unroll
        for (int p = 0; p < 2; p++) {
            float v = rs[i][p];
            v += __shfl_xor_sync(0xffffffffu, v, 1);
            v += __shfl_xor_sync(0xffffffffu, v, 2);
            if (t4 == 0) atomicAdd(&rsums[wm * 64 + i * 16 + g + p * 8], v);
        }
    __syncthreads();
    if (t < 128) rowsum[(size_t)h * SEQ + m0 + t] = rsums[t];
}

// ===========================================================================
// Pass 2: fused scores-recompute + softmax-write + PV, warp layout 8(m)x1(n).
// Each warp owns 16 rows; P stays in registers (C-frag -> A-frag via quad
// shuffles), no Ps smem, one less sync. Per 64-key tile:
//   S = Q K^T (8x8 mma), per k-chunk j: p=exp(S/8)*sinv -> att (STG.64),
//   shuffle-convert -> PV mma into ctx.
// ===========================================================================
#define P2_QS 0
#define P2_KS (128 * APAD)
#define P2_VS (P2_KS + 64 * APAD)
#define P2_SI (P2_VS + 64 * BPAD)
#define P2_SMEM_BYTES ((P2_SI + 128) * 4)

__global__ __launch_bounds__(256, 2) void fused_att_kernel(
    const float* __restrict__ Q, const float* __restrict__ Km,
    const float* __restrict__ Vm, const float* __restrict__ rowsum,
    float* __restrict__ att, float* __restrict__ Ctx)
{
    extern __shared__ float sm[];
    float* Qs = sm + P2_QS;
    float* Ks = sm + P2_KS;
    float* Vs = sm + P2_VS;
    float* sinv = sm + P2_SI;

    const int t = threadIdx.x, lane = t & 31, wid = t >> 5;
    const int g = lane >> 2, t4 = lane & 3;
    const int m0 = blockIdx.x * 128, h = blockIdx.y, kh = h / NREP;

    // Q tile (held all iterations)
#pragma unroll
    for (int i = 0; i < 8; i++) {
        int e = t + i * 256;
        int r = e >> 4, q = e & 15;
        float4 v = *(const float4*)(Q + (size_t)(m0 + r) * (HQ * HD) + h * HD + q * 4);
        *(float4*)&Qs[r * APAD + q * 4] = tf32x4(v);
    }
    if (t < 128) sinv[t] = 1.0f / rowsum[(size_t)h * SEQ + m0 + t];
    __syncthreads();

    // this warp's rows and their inverse sums
    const int rl  = wid * 16 + g;        // local row (0..127)
    const float inv_lo = sinv[rl];
    const float inv_hi = sinv[rl + 8];

    // shuffle source lanes for C-frag -> A-frag conversion
    const int src1 = (lane & ~3) | (t4 >> 1);
    const int src2 = src1 + 2;
    const bool odd = (t4 & 1);

    float ctx[8][4];
#pragma unroll
    for (int j = 0; j < 8; j++)
#pragma unroll
        for (int c = 0; c < 4; c++) ctx[j][c] = 0.f;

    float* atth = att + (size_t)h * SEQ * SEQ;

    for (int it = 0; it < SEQ / 64; it++) {
        const int k0 = it * 64;
        // prefetch K,V tiles 64x64 to regs
        float4 kv[4], vv[4];
#pragma unroll
        for (int i = 0; i < 4; i++) {
            int e = t + i * 256;
            int r = e >> 4, q = e & 15;
            kv[i] = tf32x4(*(const float4*)(Km + (size_t)(k0 + r) * (HKV * HD) + kh * HD + q * 4));
            vv[i] = tf32x4(*(const float4*)(Vm + (size_t)(k0 + r) * (HKV * HD) + kh * HD + q * 4));
        }
        __syncthreads();   // previous iter's smem reads done
#pragma unroll
        for (int i = 0; i < 4; i++) {
            int e = t + i * 256;
            int r = e >> 4, q = e & 15;
            *(float4*)&Ks[r * APAD + q * 4] = kv[i];
            *(float4*)&Vs[r * BPAD + q * 4] = vv[i];
        }
        __syncthreads();

        // ---- scores: 16 rows x 64 cols, 8 k-steps x 8 n-chunks
        float sacc[8][4];
#pragma unroll
        for (int j = 0; j < 8; j++)
#pragma unroll
            for (int c = 0; c < 4; c++) sacc[j][c] = 0.f;

#pragma unroll
        for (int ks = 0; ks < 8; ks++) {
            const int kk = ks * 8;
            uint32_t A[4] = {
                fbits(Qs[rl * APAD + kk + t4]),
                fbits(Qs[(rl + 8) * APAD + kk + t4]),
                fbits(Qs[rl * APAD + kk + t4 + 4]),
                fbits(Qs[(rl + 8) * APAD + kk + t4 + 4]) };
#pragma unroll
            for (int j = 0; j < 8; j++) {
                int n = j * 8 + g;
                uint32_t B[2] = {
                    fbits(Ks[n * APAD + kk + t4]),
                    fbits(Ks[n * APAD + kk + t4 + 4]) };
                mma_tf32(sacc[j], A, B);
            }
        }

        // ---- per k-chunk: epilogue + att store + frag-shuffle + PV mma
        const size_t rowbase = (size_t)(m0 + rl) * SEQ + k0;
#pragma unroll
        for (int j = 0; j < 8; j++) {
            float p0 = __expf(sacc[j][0] * 0.125f) * inv_lo;
            float p1 = __expf(sacc[j][1] * 0.125f) * inv_lo;
            float p2 = __expf(sacc[j][2] * 0.125f) * inv_hi;
            float p3 = __expf(sacc[j][3] * 0.125f) * inv_hi;

            // att store: cols j*8 + 2*t4 (+1); quad covers the 32B sector
            int cj = j * 8 + t4 * 2;
            *(float2*)(atth + rowbase + cj) = make_float2(p0, p1);
            *(float2*)(atth + rowbase + 8 * SEQ + cj) = make_float2(p2, p3);

            // tf32 round, then C-frag -> A-frag within quad
            uint32_t t0 = f2tf32_bits(p0), t1 = f2tf32_bits(p1);
            uint32_t t2 = f2tf32_bits(p2), t3 = f2tf32_bits(p3);
            uint32_t u0 = __shfl_sync(0xffffffffu, t0, src1);
            uint32_t u1 = __shfl_sync(0xffffffffu, t1, src1);
            uint32_t v0 = __shfl_sync(0xffffffffu, t0, src2);
            uint32_t v1 = __shfl_sync(0xffffffffu, t1, src2);
            uint32_t w0 = __shfl_sync(0xffffffffu, t2, src1);
            uint32_t w1 = __shfl_sync(0xffffffffu, t3, src1);
            uint32_t z0 = __shfl_sync(0xffffffffu, t2, src2);
            uint32_t z1 = __shfl_sync(0xffffffffu, t3, src2);
            uint32_t Apv[4];
            Apv[0] = odd ? u1 : u0;   // (row g,   col t4)
            Apv[1] = odd ? w1 : w0;   // (row g+8, col t4)
            Apv[2] = odd ? v1 : v0;   // (row g,   col t4+4)
            Apv[3] = odd ? z1 : z0;   // (row g+8, col t4+4)

            // PV: ctx[jj] += P(k-chunk j) @ V rows j*8.., cols jj*8..
            const int kb = j * 8;
#pragma unroll
            for (int jj = 0; jj < 8; jj++) {
                int n = jj * 8 + g;
                uint32_t B[2] = {
                    fbits(Vs[(kb + t4) * BPAD + n]),
                    fbits(Vs[(kb + t4 + 4) * BPAD + n]) };
                mma_tf32(ctx[jj], Apv, B);
            }
        }
    }

    // store context: rows m0+rl, m0+rl+8; cols h*HD + jj*8 + 2t4
#pragma unroll
    for (int jj = 0; jj < 8; jj++) {
        int col = h * HD + jj * 8 + t4 * 2;
        *(float2*)(Ctx + (size_t)(m0 + rl) * (HQ * HD) + col) =
            make_float2(ctx[jj][0], ctx[jj][1]);
        *(float2*)(Ctx + (size_t)(m0 + rl + 8) * (HQ * HD) + col) =
            make_float2(ctx[jj][2], ctx[jj][3]);
    }
}

// ===========================================================================
// Combined QKV projection (one kernel, 12 n-segments) + generic proj GEMM.
// Tiles: M=128 x N=64, K step 64. Warps 4(m) x 2(n).
// ===========================================================================
#define PJ_AS 0
#define PJ_BS (128 * APAD)
#define PJ_SMEM_BYTES ((PJ_BS + 64 * BPAD) * 4)

__device__ __forceinline__ void proj_body(
    const float* __restrict__ A, int lda,
    const float* __restrict__ B, int ldb,
    const float* __restrict__ bias,
    float* __restrict__ C, int ldc, int Kdim, int m0, int n0)
{
    extern __shared__ float sm[];
    float* As = sm + PJ_AS;
    float* Bs = sm + PJ_BS;

    const int t = threadIdx.x, lane = t & 31, wid = t >> 5;
    const int wm = wid >> 1, wn = wid & 1;
    const int g = lane >> 2, t4 = lane & 3;

    float acc[2][4][4];
#pragma unroll
    for (int i = 0; i < 2; i++)
#pragma unroll
        for (int j = 0; j < 4; j++)
#pragma unroll
            for (int c = 0; c < 4; c++) acc[i][j][c] = 0.f;

    for (int k0 = 0; k0 < Kdim; k0 += 64) {
        float4 av[8];
#pragma unroll
        for (int i = 0; i < 8; i++) {
            int e = t + i * 256;
            int r = e >> 4, q = e & 15;
            av[i] = tf32x4(*(const float4*)(A + (size_t)(m0 + r) * lda + k0 + q * 4));
        }
        float4 bv[4];
#pragma unroll
        for (int i = 0; i < 4; i++) {
            int e = t + i * 256;
            int r = e >> 4, q = e & 15;
            bv[i] = tf32x4(*(const float4*)(B + (size_t)(k0 + r) * ldb + n0 + q * 4));
        }
        __syncthreads();
#pragma unroll
        for (int i = 0; i < 8; i++) {
            int e = t + i * 256;
            int r = e >> 4, q = e & 15;
            *(float4*)&As[r * APAD + q * 4] = av[i];
        }
#pragma unroll
        for (int i = 0; i < 4; i++) {
            int e = t + i * 256;
            int r = e >> 4, q = e & 15;
            *(float4*)&Bs[r * BPAD + q * 4] = bv[i];
        }
        __syncthreads();

#pragma unroll
        for (int ks = 0; ks < 8; ks++) {
            const int kk = ks * 8;
            uint32_t Bf[4][2];
#pragma unroll
            for (int j = 0; j < 4; j++) {
                int n = wn * 32 + j * 8 + g;
                Bf[j][0] = fbits(Bs[(kk + t4) * BPAD + n]);
                Bf[j][1] = fbits(Bs[(kk + t4 + 4) * BPAD + n]);
            }
#pragma unroll
            for (int i = 0; i < 2; i++) {
                int r = wm * 32 + i * 16 + g;
                uint32_t Af[4] = {
                    fbits(As[r * APAD + kk + t4]),
                    fbits(As[(r + 8) * APAD + kk + t4]),
                    fbits(As[r * APAD + kk + t4 + 4]),
                    fbits(As[(r + 8) * APAD + kk + t4 + 4]) };
#pragma unroll
                for (int j = 0; j < 4; j++) mma_tf32(acc[i][j], Af, Bf[j]);
            }
        }
        __syncthreads();
    }

#pragma unroll
    for (int i = 0; i < 2; i++) {
        int r0 = m0 + wm * 32 + i * 16 + g;
#pragma unroll
        for (int j = 0; j < 4; j++) {
            int col = n0 + wn * 32 + j * 8 + t4 * 2;
            float b0 = bias[col], b1 = bias[col + 1];
            *(float2*)(C + (size_t)r0 * ldc + col) =
                make_float2(acc[i][j][0] + b0, acc[i][j][1] + b1);
            *(float2*)(C + (size_t)(r0 + 8) * ldc + col) =
                make_float2(acc[i][j][2] + b0, acc[i][j][3] + b1);
        }
    }
}

__global__ __launch_bounds__(256, 2) void qkv_proj_kernel(
    const float* __restrict__ x,
    const float* __restrict__ Wq, const float* __restrict__ bq,
    const float* __restrict__ Wk, const float* __restrict__ bk,
    const float* __restrict__ Wv, const float* __restrict__ bv,
    float* __restrict__ Qo, float* __restrict__ Ko, float* __restrict__ Vo)
{
    const int seg = blockIdx.x;
    const int m0 = blockIdx.y * 128;
    const float *W, *bias;
    float* C;
    int ld, n0;
    if (seg < 8)       { W = Wq; bias = bq; C = Qo; ld = HQ * HD;  n0 = seg * 64; }
    else if (seg < 10) { W = Wk; bias = bk; C = Ko; ld = HKV * HD; n0 = (seg - 8) * 64; }
    else               { W = Wv; bias = bv; C = Vo; ld = HKV * HD; n0 = (seg - 10) * 64; }
    proj_body(x, DIMX, W, ld, bias, C, ld, DIMX, m0, n0);
}

__global__ __launch_bounds__(256, 2) void out_proj_kernel(
    const float* __restrict__ Ctx, const float* __restrict__ Wo,
    const float* __restrict__ bo, float* __restrict__ out)
{
    proj_body(Ctx, HQ * HD, Wo, DIMX, bo, out, DIMX, HQ * HD,
              blockIdx.y * 128, blockIdx.x * 64);
}

// ===========================================================================
extern "C" void kernel_launch(void* const* d_in, const int* in_sizes, int n_in,
                              void* d_out, int out_size)
{
    const float* x  = (const float*)d_in[0];
    const float* Wq = (const float*)d_in[1];
    const float* bq = (const float*)d_in[2];
    const float* Wk = (const float*)d_in[3];
    const float* bk = (const float*)d_in[4];
    const float* Wv = (const float*)d_in[5];
    const float* bv = (const float*)d_in[6];
    const float* Wo = (const float*)d_in[7];
    const float* bo = (const float*)d_in[8];

    float* out = (float*)d_out;                 // [4096, 768]
    float* att = out + (size_t)SEQ * DIMX;      // [8, 4096, 4096]

    void* p;
    cudaGetSymbolAddress(&p, g_Q);      float* Qp = (float*)p;
    cudaGetSymbolAddress(&p, g_K);      float* Kp = (float*)p;
    cudaGetSymbolAddress(&p, g_V);      float* Vp = (float*)p;
    cudaGetSymbolAddress(&p, g_C);      float* Cp = (float*)p;
    cudaGetSymbolAddress(&p, g_rowsum); float* Rp = (float*)p;

    cudaFuncSetAttribute(rowsum_kernel,
        cudaFuncAttributeMaxDynamicSharedMemorySize, RS_SMEM_BYTES);
    cudaFuncSetAttribute(fused_att_kernel,
        cudaFuncAttributeMaxDynamicSharedMemorySize, P2_SMEM_BYTES);
    cudaFuncSetAttribute(qkv_proj_kernel,
        cudaFuncAttributeMaxDynamicSharedMemorySize, PJ_SMEM_BYTES);
    cudaFuncSetAttribute(out_proj_kernel,
        cudaFuncAttributeMaxDynamicSharedMemorySize, PJ_SMEM_BYTES);

    dim3 blk(256);

    // QKV projections (single kernel, 12 n-segments x 32 m-tiles)
    qkv_proj_kernel<<<dim3(12, SEQ / 128), blk, PJ_SMEM_BYTES>>>(
        x, Wq, bq, Wk, bk, Wv, bv, Qp, Kp, Vp);

    // Pass 1: rowsums
    rowsum_kernel<<<dim3(SEQ / 128, HQ), blk, RS_SMEM_BYTES>>>(Qp, Kp, Rp);

    // Pass 2: fused scores + softmax write + PV (register-resident P)
    fused_att_kernel<<<dim3(SEQ / 128, HQ), blk, P2_SMEM_BYTES>>>(
        Qp, Kp, Vp, Rp, att, Cp);

    // out = context @ Wo + bo
    out_proj_kernel<<<dim3(DIMX / 64, SEQ / 128), blk, PJ_SMEM_BYTES>>>(
        Cp, Wo, bo, out);
}

// round 6
// speedup vs baseline: 1.5260x; 1.5260x over previous
#include <cuda_runtime.h>
#include <cuda_fp16.h>
#include <cstdint>

// Problem constants
#define DIMX 768
#define HQ   8
#define HKV  2
#define HD   64
#define SEQ  4096
#define NREP (HQ / HKV)   // 4

// Scratch (allocation-free rule: __device__ globals)
__device__ float  g_Q[SEQ * HQ * HD];     // [4096, 512]  fp32
__device__ float  g_K[SEQ * HKV * HD];    // [4096, 128]  fp32
__device__ float  g_V[SEQ * HKV * HD];    // [4096, 128]  fp32
__device__ __half g_Kh[SEQ * HKV * HD];   // [4096, 128]  half
__device__ __half g_Vt[HKV * HD * SEQ];   // [2][64][4096] half, transposed
__device__ float  g_C[SEQ * HQ * HD];     // context [4096, 512]
__device__ float  g_rowsum[HQ * SEQ];     // exp row sums

// ===========================================================================
// helpers
// ===========================================================================
__device__ __forceinline__ float f2tf32(float x) {
    uint32_t u;
    asm("cvt.rna.tf32.f32 %0, %1;" : "=r"(u) : "f"(x));
    return __uint_as_float(u);
}
__device__ __forceinline__ float4 tf32x4(float4 v) {
    float4 w;
    w.x = f2tf32(v.x); w.y = f2tf32(v.y); w.z = f2tf32(v.z); w.w = f2tf32(v.w);
    return w;
}
__device__ __forceinline__ void mma_tf32(float* c, const uint32_t* a, const uint32_t* b) {
    asm volatile(
        "mma.sync.aligned.m16n8k8.row.col.f32.tf32.tf32.f32 "
        "{%0,%1,%2,%3}, {%4,%5,%6,%7}, {%8,%9}, {%0,%1,%2,%3};"
        : "+f"(c[0]), "+f"(c[1]), "+f"(c[2]), "+f"(c[3])
        : "r"(a[0]), "r"(a[1]), "r"(a[2]), "r"(a[3]), "r"(b[0]), "r"(b[1]));
}
// fp16 m16n8k16, fp32 accumulate
__device__ __forceinline__ void mma_f16(float* c, const uint32_t* a, uint32_t b0, uint32_t b1) {
    asm volatile(
        "mma.sync.aligned.m16n8k16.row.col.f32.f16.f16.f32 "
        "{%0,%1,%2,%3}, {%4,%5,%6,%7}, {%8,%9}, {%0,%1,%2,%3};"
        : "+f"(c[0]), "+f"(c[1]), "+f"(c[2]), "+f"(c[3])
        : "r"(a[0]), "r"(a[1]), "r"(a[2]), "r"(a[3]), "r"(b0), "r"(b1));
}
__device__ __forceinline__ uint32_t pack2(float a, float b) {
    __half2 h = __floats2half2_rn(a, b);   // .x = a (low), .y = b (high)
    return *reinterpret_cast<uint32_t*>(&h);
}
__device__ __forceinline__ uint32_t fbits(float x) { return __float_as_uint(x); }

#define APAD 68   // fp32 row-major tiles (projections)
#define BPAD 72
#define HPAD 72   // half tiles: stride in halves (144B rows, 16B aligned)

// ===========================================================================
// Prep: fp32 K -> half Kh (elementwise)
// ===========================================================================
__global__ void k2h_kernel(const float* __restrict__ K, __half* __restrict__ Kh)
{
    int i = blockIdx.x * 256 + threadIdx.x;         // indexes float4s
    float4 v = *(const float4*)(K + (size_t)i * 4);
    uint2 o;
    o.x = pack2(v.x, v.y);
    o.y = pack2(v.z, v.w);
    *(uint2*)((char*)Kh + (size_t)i * 8) = o;
}

// ===========================================================================
// Prep: fp32 V [s][kh*64+d] -> half Vt [kh][d][s]
// ===========================================================================
__global__ void vt_kernel(const float* __restrict__ V, __half* __restrict__ Vt)
{
    __shared__ float tile[32][33];
    const int kh = blockIdx.z;
    const int s0 = blockIdx.x * 32;
    const int d0 = blockIdx.y * 32;
    const int tx = threadIdx.x, ty = threadIdx.y;
#pragma unroll
    for (int i = 0; i < 32; i += 8)
        tile[ty + i][tx] = V[(size_t)(s0 + ty + i) * (HKV * HD) + kh * HD + d0 + tx];
    __syncthreads();
#pragma unroll
    for (int i = 0; i < 32; i += 8)
        Vt[(size_t)kh * HD * SEQ + (size_t)(d0 + ty + i) * SEQ + s0 + tx] =
            __float2half_rn(tile[tx][ty + i]);
}

// ===========================================================================
// Pass 1 (fp16): rowsum[h, m] = sum_n exp(Q.K/8). 8 warps x 16 rows.
// Q fragments persistent in registers (loaded once from gmem).
// ===========================================================================
__global__ __launch_bounds__(256) void rowsum_kernel(
    const float* __restrict__ Q, const __half* __restrict__ Kh,
    float* __restrict__ rowsum)
{
    __shared__ __half Ks[128 * HPAD];

    const int t = threadIdx.x, lane = t & 31, wid = t >> 5;
    const int g = lane >> 2, t4 = lane & 3;
    const int m0 = blockIdx.x * 128, h = blockIdx.y, kh = h / NREP;

    // persistent Q fragments: 4 k16-chunks x 4 regs
    uint32_t qf[4][4];
    {
        const float* q0 = Q + (size_t)(m0 + wid * 16 + g) * (HQ * HD) + h * HD;
        const float* q1 = q0 + (size_t)8 * (HQ * HD);
#pragma unroll
        for (int ks = 0; ks < 4; ks++) {
            int c = ks * 16 + t4 * 2;
            qf[ks][0] = pack2(q0[c], q0[c + 1]);
            qf[ks][1] = pack2(q1[c], q1[c + 1]);
            qf[ks][2] = pack2(q0[c + 8], q0[c + 9]);
            qf[ks][3] = pack2(q1[c + 8], q1[c + 9]);
        }
    }

    float rs0 = 0.f, rs1 = 0.f;

    for (int it = 0; it < SEQ / 128; it++) {
        const int n0 = it * 128;
        __syncthreads();
#pragma unroll
        for (int i = 0; i < 4; i++) {
            int e = t + i * 256;
            int r = e >> 3, seg = e & 7;
            *(uint4*)&Ks[r * HPAD + seg * 8] =
                *(const uint4*)(Kh + (size_t)(n0 + r) * (HKV * HD) + kh * HD + seg * 8);
        }
        __syncthreads();

#pragma unroll
        for (int jg = 0; jg < 2; jg++) {
            float sacc[8][4];
#pragma unroll
            for (int j = 0; j < 8; j++)
#pragma unroll
                for (int c = 0; c < 4; c++) sacc[j][c] = 0.f;
#pragma unroll
            for (int ks = 0; ks < 4; ks++) {
                const int cb = ks * 16 + t4 * 2;
#pragma unroll
                for (int j = 0; j < 8; j++) {
                    int n = (jg * 8 + j) * 8 + g;
                    uint32_t b0 = *(const uint32_t*)&Ks[n * HPAD + cb];
                    uint32_t b1 = *(const uint32_t*)&Ks[n * HPAD + cb + 8];
                    mma_f16(sacc[j], qf[ks], b0, b1);
                }
            }
#pragma unroll
            for (int j = 0; j < 8; j++) {
                rs0 += __expf(sacc[j][0] * 0.125f) + __expf(sacc[j][1] * 0.125f);
                rs1 += __expf(sacc[j][2] * 0.125f) + __expf(sacc[j][3] * 0.125f);
            }
        }
    }

    // quad reduction (t4 lanes hold disjoint column groups of same rows)
    rs0 += __shfl_xor_sync(0xffffffffu, rs0, 1);
    rs0 += __shfl_xor_sync(0xffffffffu, rs0, 2);
    rs1 += __shfl_xor_sync(0xffffffffu, rs1, 1);
    rs1 += __shfl_xor_sync(0xffffffffu, rs1, 2);
    if (t4 == 0) {
        rowsum[(size_t)h * SEQ + m0 + wid * 16 + g] = rs0;
        rowsum[(size_t)h * SEQ + m0 + wid * 16 + g + 8] = rs1;
    }
}

// ===========================================================================
// Pass 2 (fp16): fused scores-recompute + softmax write + PV.
// 8 warps x 16 rows. P reuses scores C-frags as PV A-frags (pure packs).
// ===========================================================================
__global__ __launch_bounds__(256, 2) void fused_att_kernel(
    const float* __restrict__ Q, const __half* __restrict__ Kh,
    const __half* __restrict__ Vt, const float* __restrict__ rowsum,
    float* __restrict__ att, float* __restrict__ Ctx)
{
    __shared__ __half Ks[64 * HPAD];
    __shared__ __half Vs[64 * HPAD];
    __shared__ float sinv[128];

    const int t = threadIdx.x, lane = t & 31, wid = t >> 5;
    const int g = lane >> 2, t4 = lane & 3;
    const int m0 = blockIdx.x * 128, h = blockIdx.y, kh = h / NREP;

    if (t < 128) sinv[t] = 1.0f / rowsum[(size_t)h * SEQ + m0 + t];

    // persistent Q fragments
    uint32_t qf[4][4];
    {
        const float* q0 = Q + (size_t)(m0 + wid * 16 + g) * (HQ * HD) + h * HD;
        const float* q1 = q0 + (size_t)8 * (HQ * HD);
#pragma unroll
        for (int ks = 0; ks < 4; ks++) {
            int c = ks * 16 + t4 * 2;
            qf[ks][0] = pack2(q0[c], q0[c + 1]);
            qf[ks][1] = pack2(q1[c], q1[c + 1]);
            qf[ks][2] = pack2(q0[c + 8], q0[c + 9]);
            qf[ks][3] = pack2(q1[c + 8], q1[c + 9]);
        }
    }
    __syncthreads();

    const int rl = wid * 16 + g;
    const float inv_lo = sinv[rl];
    const float inv_hi = sinv[rl + 8];
    const __half* vth = Vt + (size_t)kh * HD * SEQ;

    float ctx[8][4];
#pragma unroll
    for (int j = 0; j < 8; j++)
#pragma unroll
        for (int c = 0; c < 4; c++) ctx[j][c] = 0.f;

    float* atth = att + (size_t)h * SEQ * SEQ;

    for (int it = 0; it < SEQ / 64; it++) {
        const int k0 = it * 64;
        __syncthreads();   // previous iter's smem reads done
        // fill K tile (64 keys x 64 d halves) and V tile ([d][key] halves)
#pragma unroll
        for (int i = 0; i < 2; i++) {
            int e = t + i * 256;
            int r = e >> 3, seg = e & 7;
            *(uint4*)&Ks[r * HPAD + seg * 8] =
                *(const uint4*)(Kh + (size_t)(k0 + r) * (HKV * HD) + kh * HD + seg * 8);
            *(uint4*)&Vs[r * HPAD + seg * 8] =
                *(const uint4*)(vth + (size_t)r * SEQ + k0 + seg * 8);
        }
        __syncthreads();

        // ---- scores: 16 rows x 64 keys, 4 k16-steps x 8 n-chunks
        float sacc[8][4];
#pragma unroll
        for (int j = 0; j < 8; j++)
#pragma unroll
            for (int c = 0; c < 4; c++) sacc[j][c] = 0.f;

#pragma unroll
        for (int ks = 0; ks < 4; ks++) {
            const int cb = ks * 16 + t4 * 2;
#pragma unroll
            for (int j = 0; j < 8; j++) {
                int n = j * 8 + g;
                uint32_t b0 = *(const uint32_t*)&Ks[n * HPAD + cb];
                uint32_t b1 = *(const uint32_t*)&Ks[n * HPAD + cb + 8];
                mma_f16(sacc[j], qf[ks], b0, b1);
            }
        }

        // ---- epilogue: p = exp(s/8)*inv -> att (fp32) + pack to fp16 A-frags
        const size_t rowbase = (size_t)(m0 + rl) * SEQ + k0;
        uint32_t pk[8][2];
#pragma unroll
        for (int j = 0; j < 8; j++) {
            float p0 = __expf(sacc[j][0] * 0.125f) * inv_lo;
            float p1 = __expf(sacc[j][1] * 0.125f) * inv_lo;
            float p2 = __expf(sacc[j][2] * 0.125f) * inv_hi;
            float p3 = __expf(sacc[j][3] * 0.125f) * inv_hi;
            int cj = j * 8 + t4 * 2;
            *(float2*)(atth + rowbase + cj) = make_float2(p0, p1);
            *(float2*)(atth + rowbase + 8 * SEQ + cj) = make_float2(p2, p3);
            pk[j][0] = pack2(p0, p1);
            pk[j][1] = pack2(p2, p3);
        }

        // ---- PV: ctx += P @ V   (A-frags = packed C-frags, B from Vs[d][key])
#pragma unroll
        for (int kc = 0; kc < 4; kc++) {
            uint32_t A[4] = { pk[2 * kc][0], pk[2 * kc][1],
                              pk[2 * kc + 1][0], pk[2 * kc + 1][1] };
            const int kb = kc * 16 + t4 * 2;
#pragma unroll
            for (int jj = 0; jj < 8; jj++) {
                int nn = jj * 8 + g;
                uint32_t b0 = *(const uint32_t*)&Vs[nn * HPAD + kb];
                uint32_t b1 = *(const uint32_t*)&Vs[nn * HPAD + kb + 8];
                mma_f16(ctx[jj], A, b0, b1);
            }
        }
    }

    // store context
#pragma unroll
    for (int jj = 0; jj < 8; jj++) {
        int col = h * HD + jj * 8 + t4 * 2;
        *(float2*)(Ctx + (size_t)(m0 + rl) * (HQ * HD) + col) =
            make_float2(ctx[jj][0], ctx[jj][1]);
        *(float2*)(Ctx + (size_t)(m0 + rl + 8) * (HQ * HD) + col) =
            make_float2(ctx[jj][2], ctx[jj][3]);
    }
}

// ===========================================================================
// Projections (tf32 mma, unchanged from round 4): C = A @ B + bias
// ===========================================================================
#define PJ_AS 0
#define PJ_BS (128 * APAD)
#define PJ_SMEM_BYTES ((PJ_BS + 64 * BPAD) * 4)

__device__ __forceinline__ void proj_body(
    const float* __restrict__ A, int lda,
    const float* __restrict__ B, int ldb,
    const float* __restrict__ bias,
    float* __restrict__ C, int ldc, int Kdim, int m0, int n0)
{
    extern __shared__ float sm[];
    float* As = sm + PJ_AS;
    float* Bs = sm + PJ_BS;

    const int t = threadIdx.x, lane = t & 31, wid = t >> 5;
    const int wm = wid >> 1, wn = wid & 1;
    const int g = lane >> 2, t4 = lane & 3;

    float acc[2][4][4];
#pragma unroll
    for (int i = 0; i < 2; i++)
#pragma unroll
        for (int j = 0; j < 4; j++)
#pragma unroll
            for (int c = 0; c < 4; c++) acc[i][j][c] = 0.f;

    for (int k0 = 0; k0 < Kdim; k0 += 64) {
        float4 av[8];
#pragma unroll
        for (int i = 0; i < 8; i++) {
            int e = t + i * 256;
            int r = e >> 4, q = e & 15;
            av[i] = tf32x4(*(const float4*)(A + (size_t)(m0 + r) * lda + k0 + q * 4));
        }
        float4 bv[4];
#pragma unroll
        for (int i = 0; i < 4; i++) {
            int e = t + i * 256;
            int r = e >> 4, q = e & 15;
            bv[i] = tf32x4(*(const float4*)(B + (size_t)(k0 + r) * ldb + n0 + q * 4));
        }
        __syncthreads();
#pragma unroll
        for (int i = 0; i < 8; i++) {
            int e = t + i * 256;
            int r = e >> 4, q = e & 15;
            *(float4*)&As[r * APAD + q * 4] = av[i];
        }
#pragma unroll
        for (int i = 0; i < 4; i++) {
            int e = t + i * 256;
            int r = e >> 4, q = e & 15;
            *(float4*)&Bs[r * BPAD + q * 4] = bv[i];
        }
        __syncthreads();

#pragma unroll
        for (int ks = 0; ks < 8; ks++) {
            const int kk = ks * 8;
            uint32_t Bf[4][2];
#pragma unroll
            for (int j = 0; j < 4; j++) {
                int n = wn * 32 + j * 8 + g;
                Bf[j][0] = fbits(Bs[(kk + t4) * BPAD + n]);
                Bf[j][1] = fbits(Bs[(kk + t4 + 4) * BPAD + n]);
            }
#pragma unroll
            for (int i = 0; i < 2; i++) {
                int r = wm * 32 + i * 16 + g;
                uint32_t Af[4] = {
                    fbits(As[r * APAD + kk + t4]),
                    fbits(As[(r + 8) * APAD + kk + t4]),
                    fbits(As[r * APAD + kk + t4 + 4]),
                    fbits(As[(r + 8) * APAD + kk + t4 + 4]) };
#pragma unroll
                for (int j = 0; j < 4; j++) mma_tf32(acc[i][j], Af, Bf[j]);
            }
        }
        __syncthreads();
    }

#pragma unroll
    for (int i = 0; i < 2; i++) {
        int r0 = m0 + wm * 32 + i * 16 + g;
#pragma unroll
        for (int j = 0; j < 4; j++) {
            int col = n0 + wn * 32 + j * 8 + t4 * 2;
            float b0 = bias[col], b1 = bias[col + 1];
            *(float2*)(C + (size_t)r0 * ldc + col) =
                make_float2(acc[i][j][0] + b0, acc[i][j][1] + b1);
            *(float2*)(C + (size_t)(r0 + 8) * ldc + col) =
                make_float2(acc[i][j][2] + b0, acc[i][j][3] + b1);
        }
    }
}

__global__ __launch_bounds__(256, 2) void qkv_proj_kernel(
    const float* __restrict__ x,
    const float* __restrict__ Wq, const float* __restrict__ bq,
    const float* __restrict__ Wk, const float* __restrict__ bk,
    const float* __restrict__ Wv, const float* __restrict__ bv,
    float* __restrict__ Qo, float* __restrict__ Ko, float* __restrict__ Vo)
{
    const int seg = blockIdx.x;
    const int m0 = blockIdx.y * 128;
    const float *W, *bias;
    float* C;
    int ld, n0;
    if (seg < 8)       { W = Wq; bias = bq; C = Qo; ld = HQ * HD;  n0 = seg * 64; }
    else if (seg < 10) { W = Wk; bias = bk; C = Ko; ld = HKV * HD; n0 = (seg - 8) * 64; }
    else               { W = Wv; bias = bv; C = Vo; ld = HKV * HD; n0 = (seg - 10) * 64; }
    proj_body(x, DIMX, W, ld, bias, C, ld, DIMX, m0, n0);
}

__global__ __launch_bounds__(256, 2) void out_proj_kernel(
    const float* __restrict__ Ctx, const float* __restrict__ Wo,
    const float* __restrict__ bo, float* __restrict__ out)
{
    proj_body(Ctx, HQ * HD, Wo, DIMX, bo, out, DIMX, HQ * HD,
              blockIdx.y * 128, blockIdx.x * 64);
}

// ===========================================================================
extern "C" void kernel_launch(void* const* d_in, const int* in_sizes, int n_in,
                              void* d_out, int out_size)
{
    const float* x  = (const float*)d_in[0];
    const float* Wq = (const float*)d_in[1];
    const float* bq = (const float*)d_in[2];
    const float* Wk = (const float*)d_in[3];
    const float* bk = (const float*)d_in[4];
    const float* Wv = (const float*)d_in[5];
    const float* bv = (const float*)d_in[6];
    const float* Wo = (const float*)d_in[7];
    const float* bo = (const float*)d_in[8];

    float* out = (float*)d_out;                 // [4096, 768]
    float* att = out + (size_t)SEQ * DIMX;      // [8, 4096, 4096]

    void* p;
    cudaGetSymbolAddress(&p, g_Q);      float*  Qp  = (float*)p;
    cudaGetSymbolAddress(&p, g_K);      float*  Kp  = (float*)p;
    cudaGetSymbolAddress(&p, g_V);      float*  Vp  = (float*)p;
    cudaGetSymbolAddress(&p, g_Kh);     __half* Khp = (__half*)p;
    cudaGetSymbolAddress(&p, g_Vt);     __half* Vtp = (__half*)p;
    cudaGetSymbolAddress(&p, g_C);      float*  Cp  = (float*)p;
    cudaGetSymbolAddress(&p, g_rowsum); float*  Rp  = (float*)p;

    cudaFuncSetAttribute(qkv_proj_kernel,
        cudaFuncAttributeMaxDynamicSharedMemorySize, PJ_SMEM_BYTES);
    cudaFuncSetAttribute(out_proj_kernel,
        cudaFuncAttributeMaxDynamicSharedMemorySize, PJ_SMEM_BYTES);

    dim3 blk(256);

    // QKV projections (tf32, fp32 outputs)
    qkv_proj_kernel<<<dim3(12, SEQ / 128), blk, PJ_SMEM_BYTES>>>(
        x, Wq, bq, Wk, bk, Wv, bv, Qp, Kp, Vp);

    // preps: K -> half, V -> transposed half
    k2h_kernel<<<(SEQ * HKV * HD) / 4 / 256, blk>>>(Kp, Khp);
    vt_kernel<<<dim3(SEQ / 32, HD / 32, HKV), dim3(32, 8)>>>(Vp, Vtp);

    // Pass 1: rowsums (fp16 mma)
    rowsum_kernel<<<dim3(SEQ / 128, HQ), blk>>>(Qp, Khp, Rp);

    // Pass 2: fused scores + softmax write + PV (fp16 mma, register P reuse)
    fused_att_kernel<<<dim3(SEQ / 128, HQ), blk>>>(Qp, Khp, Vtp, Rp, att, Cp);

    // out = context @ Wo + bo
    out_proj_kernel<<<dim3(DIMX / 64, SEQ / 128), blk, PJ_SMEM_BYTES>>>(
        Cp, Wo, bo, out);
}